// round 7
// baseline (speedup 1.0000x reference)
#include <cuda_runtime.h>
#include <cuda_bf16.h>
#include <math.h>
#include <stdint.h>

// ---------------- constants ----------------
#define BATCH 4
#define SEQ   2048
#define EMB   2048
#define NHEAD 16
#define HDIM  128
#define MROWS (BATCH*SEQ)               // 8192
#define ELEMS ((size_t)BATCH*SEQ*EMB)   // 16777216
#define L2E   1.4426950408889634f
#define RMS_EPS 1.1920929e-07f

// ---------------- scratch (device globals: allocation-free) ----------------
__device__ __nv_bfloat16 g_ahi[ELEMS];
__device__ __nv_bfloat16 g_alo[ELEMS];
__device__ __nv_bfloat16 g_wthi[(size_t)4*EMB*EMB];
__device__ __nv_bfloat16 g_wtlo[(size_t)4*EMB*EMB];
__device__ __nv_bfloat16 g_qh[ELEMS];
__device__ __nv_bfloat16 g_ql[ELEMS];
__device__ __nv_bfloat16 g_kh[ELEMS];
__device__ __nv_bfloat16 g_kl[ELEMS];
__device__ __nv_bfloat16 g_vh[ELEMS];
__device__ __nv_bfloat16 g_vl[ELEMS];
__device__ float g_cos[SEQ*64];
__device__ float g_sin[SEQ*64];

// =====================================================================
// PTX helpers (standard sm_80+ instructions; valid on plain sm_103)
// =====================================================================
__device__ __forceinline__ uint32_t smem_to_u32(const void* p) {
    uint32_t a;
    asm("{ .reg .u64 t; cvta.to.shared.u64 t, %1; cvt.u32.u64 %0, t; }"
        : "=r"(a) : "l"(p));
    return a;
}

__device__ __forceinline__ void ldsm4(uint32_t* r, uint32_t addr) {
    asm volatile("ldmatrix.sync.aligned.m8n8.x4.shared.b16 {%0,%1,%2,%3}, [%4];"
        : "=r"(r[0]), "=r"(r[1]), "=r"(r[2]), "=r"(r[3]) : "r"(addr));
}
__device__ __forceinline__ void ldsm4t(uint32_t* r, uint32_t addr) {
    asm volatile("ldmatrix.sync.aligned.m8n8.x4.trans.shared.b16 {%0,%1,%2,%3}, [%4];"
        : "=r"(r[0]), "=r"(r[1]), "=r"(r[2]), "=r"(r[3]) : "r"(addr));
}

__device__ __forceinline__ void mma_bf16(float* c, const uint32_t* a, const uint32_t* b) {
    asm volatile(
        "mma.sync.aligned.m16n8k16.row.col.f32.bf16.bf16.f32 "
        "{%0,%1,%2,%3}, {%4,%5,%6,%7}, {%8,%9}, {%0,%1,%2,%3};"
        : "+f"(c[0]), "+f"(c[1]), "+f"(c[2]), "+f"(c[3])
        : "r"(a[0]), "r"(a[1]), "r"(a[2]), "r"(a[3]), "r"(b[0]), "r"(b[1]));
}

__device__ __forceinline__ uint32_t pack_bf16x2(float lo, float hi) {
    uint32_t r;
    asm("cvt.rn.bf16x2.f32 %0, %1, %2;" : "=r"(r) : "f"(hi), "f"(lo));
    return r;
}

// fast exp2 (single SASS MUFU.EX2)
__device__ __forceinline__ float ex2(float x) {
    float y;
    asm("ex2.approx.f32 %0, %1;" : "=f"(y) : "f"(x));
    return y;
}

#define CP_ASYNC16(dst, src) \
    asm volatile("cp.async.cg.shared.global [%0], [%1], 16;" :: "r"(dst), "l"(src) : "memory")
#define CP_COMMIT() asm volatile("cp.async.commit_group;" ::: "memory")
#define CP_WAIT1()  asm volatile("cp.async.wait_group 1;" ::: "memory")
#define CP_WAIT0()  asm volatile("cp.async.wait_group 0;" ::: "memory")

// =====================================================================
// split: fp32 -> bf16 hi + bf16 lo (residual)
// =====================================================================
__global__ __launch_bounds__(256) void split_kernel(
    const float* __restrict__ in,
    __nv_bfloat16* __restrict__ hi, __nv_bfloat16* __restrict__ lo, int n4)
{
    int i = blockIdx.x * 256 + threadIdx.x;
    if (i >= n4) return;
    float4 v = ((const float4*)in)[i];
    __nv_bfloat16 h0 = __float2bfloat16(v.x);
    __nv_bfloat16 h1 = __float2bfloat16(v.y);
    __nv_bfloat16 h2 = __float2bfloat16(v.z);
    __nv_bfloat16 h3 = __float2bfloat16(v.w);
    __nv_bfloat16 l0 = __float2bfloat16(v.x - __bfloat162float(h0));
    __nv_bfloat16 l1 = __float2bfloat16(v.y - __bfloat162float(h1));
    __nv_bfloat16 l2 = __float2bfloat16(v.z - __bfloat162float(h2));
    __nv_bfloat16 l3 = __float2bfloat16(v.w - __bfloat162float(h3));
    __nv_bfloat162* hp = (__nv_bfloat162*)(hi + 4 * (size_t)i);
    __nv_bfloat162* lp = (__nv_bfloat162*)(lo + 4 * (size_t)i);
    hp[0] = __nv_bfloat162(h0, h1); hp[1] = __nv_bfloat162(h2, h3);
    lp[0] = __nv_bfloat162(l0, l1); lp[1] = __nv_bfloat162(l2, l3);
}

// =====================================================================
// 4 weights at once: transpose + split, blockIdx.z selects the weight
// =====================================================================
__global__ __launch_bounds__(256) void wsplit4_kernel(
    const float* __restrict__ w0, const float* __restrict__ w1,
    const float* __restrict__ w2, const float* __restrict__ w3,
    __nv_bfloat16* __restrict__ hi_base, __nv_bfloat16* __restrict__ lo_base)
{
    __shared__ float tile[32][33];
    const int z = blockIdx.z;
    const float* w = (z == 0) ? w0 : (z == 1) ? w1 : (z == 2) ? w2 : w3;
    __nv_bfloat16* hi = hi_base + (size_t)z * EMB * EMB;
    __nv_bfloat16* lo = lo_base + (size_t)z * EMB * EMB;

    int n0 = blockIdx.x * 32, k0 = blockIdx.y * 32;
    int tx = threadIdx.x & 31, ty = threadIdx.x >> 5;
#pragma unroll
    for (int i = 0; i < 32; i += 8)
        tile[ty + i][tx] = w[(size_t)(k0 + ty + i) * EMB + n0 + tx];
    __syncthreads();
#pragma unroll
    for (int i = 0; i < 32; i += 8) {
        float v = tile[tx][ty + i];
        __nv_bfloat16 h = __float2bfloat16(v);
        size_t o = (size_t)(n0 + ty + i) * EMB + k0 + tx;
        hi[o] = h;
        lo[o] = __float2bfloat16(v - __bfloat162float(h));
    }
}

// =====================================================================
// RoPE table precompute (double precision, once)
// =====================================================================
__global__ __launch_bounds__(256) void rope_table_kernel(
    float* __restrict__ ct, float* __restrict__ st)
{
    const int idx = blockIdx.x * 256 + threadIdx.x;
    if (idx >= SEQ * 64) return;
    const int tp = idx >> 6, i = idx & 63;
    double inv = exp(-((double)i / 64.0) * log(10000.0));
    double ang = (double)tp * inv;
    double sd, cd;
    sincos(ang, &sd, &cd);
    ct[idx] = (float)cd;
    st[idx] = (float)sd;
}

// =====================================================================
// mma.sync GEMM: C = A * B^T, split bf16 3-chain, 2-stage cp.async.
// Block tile 128x256x64, 8 warps (2 x 4), warp tile 64x64.
// mode 0: write fp32 to c0 (row stride EMB).
// mode 1: QKV fused (N=6144). Per-CTA region (col0>>11):
//   0 -> Q: fused RoPE+RMSNorm+split -> qh/ql  (scale folded in)
//   1 -> K: fused RoPE+RMSNorm+split -> kh/kl
//   2 -> V: direct bf16 hi/lo -> vh/vl
// =====================================================================
#define BM 128
#define BN 256
#define BK 64
#define RSTRB 144
#define TA (128 * RSTRB)          // 18432
#define TB (256 * RSTRB)          // 36864
#define STG_B (2*TA + 2*TB)       // 110592
#define GEMM_SMEM (2 * STG_B)     // 221184
#define CSTR 257                  // fp32 epilogue smem row stride

__global__ __launch_bounds__(256) void mma_gemm_kernel(
    const __nv_bfloat16* __restrict__ Ahi, const __nv_bfloat16* __restrict__ Alo,
    const __nv_bfloat16* __restrict__ Bhi, const __nv_bfloat16* __restrict__ Blo,
    int K, int mode,
    float* __restrict__ c0,
    __nv_bfloat16* __restrict__ qh, __nv_bfloat16* __restrict__ ql,
    __nv_bfloat16* __restrict__ kh, __nv_bfloat16* __restrict__ kl,
    __nv_bfloat16* __restrict__ vh, __nv_bfloat16* __restrict__ vl,
    const float* __restrict__ ct, const float* __restrict__ st)
{
    extern __shared__ char smc[];
    const uint32_t sb = smem_to_u32(smc);
    const int t = threadIdx.x;
    const int lane = t & 31;
    const int wid = t >> 5;
    const int warp_m = wid & 1;
    const int warp_n = wid >> 1;
    const int row0 = blockIdx.y * BM;
    const int col0 = blockIdx.x * BN;

    float acc[4][8][4];
#pragma unroll
    for (int i = 0; i < 4; i++)
#pragma unroll
        for (int j = 0; j < 8; j++)
#pragma unroll
            for (int r = 0; r < 4; r++) acc[i][j][r] = 0.f;

    auto load_stage = [&](int s, int k0) {
        const uint32_t base = sb + s * STG_B;
#pragma unroll
        for (int i = 0; i < 4; i++) {
            const int idx = t + i * 256;
            const int r = idx >> 3, c = idx & 7;
            const size_t g = (size_t)(row0 + r) * K + k0 + c * 8;
            const uint32_t d = base + r * RSTRB + c * 16;
            CP_ASYNC16(d, Ahi + g);
            CP_ASYNC16(d + TA, Alo + g);
        }
#pragma unroll
        for (int i = 0; i < 8; i++) {
            const int idx = t + i * 256;
            const int r = idx >> 3, c = idx & 7;
            const size_t g = (size_t)(col0 + r) * K + k0 + c * 8;
            const uint32_t d = base + 2 * TA + r * RSTRB + c * 16;
            CP_ASYNC16(d, Bhi + g);
            CP_ASYNC16(d + TB, Blo + g);
        }
    };

    const int nIter = K / BK;
    load_stage(0, 0);
    CP_COMMIT();

    for (int it = 0; it < nIter; it++) {
        if (it + 1 < nIter) {
            load_stage((it + 1) & 1, (it + 1) * BK);
            CP_COMMIT();
            CP_WAIT1();
        } else {
            CP_WAIT0();
        }
        __syncthreads();

        const uint32_t abase = sb + (it & 1) * STG_B;
        const uint32_t bbase = abase + 2 * TA;
        const int arow = warp_m * 64 + (lane & 15);
        const int brow = warp_n * 64 + ((lane >> 4) << 3) + (lane & 7);

#pragma unroll
        for (int ks = 0; ks < 4; ks++) {
            uint32_t ah[4][4], al[4][4], bh[4][4], bl[4][4];
            const uint32_t acol = ks * 32 + ((lane >> 4) << 4);
            const uint32_t bcol = ks * 32 + (((lane >> 3) & 1) << 4);
#pragma unroll
            for (int mf = 0; mf < 4; mf++) {
                const uint32_t ad = abase + (arow + mf * 16) * RSTRB + acol;
                ldsm4(ah[mf], ad);
                ldsm4(al[mf], ad + TA);
            }
#pragma unroll
            for (int bf = 0; bf < 4; bf++) {
                const uint32_t bd = bbase + (brow + bf * 16) * RSTRB + bcol;
                ldsm4(bh[bf], bd);
                ldsm4(bl[bf], bd + TB);
            }
#pragma unroll
            for (int mf = 0; mf < 4; mf++) {
#pragma unroll
                for (int nf = 0; nf < 8; nf++) {
                    const uint32_t* bhp = &bh[nf >> 1][(nf & 1) * 2];
                    const uint32_t* blp = &bl[nf >> 1][(nf & 1) * 2];
                    mma_bf16(acc[mf][nf], ah[mf], bhp);
                    mma_bf16(acc[mf][nf], ah[mf], blp);
                    mma_bf16(acc[mf][nf], al[mf], bhp);
                }
            }
        }
        __syncthreads();
    }

    // ---- epilogue ----
    const int rloc = warp_m * 64 + (lane >> 2);
    const int nloc = warp_n * 64 + (lane & 3) * 2;

    if (mode == 0) {
#pragma unroll
        for (int mf = 0; mf < 4; mf++) {
#pragma unroll
            for (int nf = 0; nf < 8; nf++) {
                const float* a = acc[mf][nf];
                const size_t o0 = (size_t)(row0 + rloc + mf * 16) * EMB + col0 + nloc + nf * 8;
                *(float2*)(c0 + o0) = make_float2(a[0], a[1]);
                *(float2*)(c0 + o0 + 8 * EMB) = make_float2(a[2], a[3]);
            }
        }
        return;
    }

    const int whichCTA = col0 >> 11;   // 0=Q 1=K 2=V
    if (whichCTA == 2) {
        // V: direct bf16 hi/lo
#pragma unroll
        for (int mf = 0; mf < 4; mf++) {
#pragma unroll
            for (int nf = 0; nf < 8; nf++) {
                const float* a = acc[mf][nf];
                const size_t o0 = (size_t)(row0 + rloc + mf * 16) * EMB
                                  + (col0 & 2047) + nloc + nf * 8;
                uint32_t h0 = pack_bf16x2(a[0], a[1]);
                uint32_t h1 = pack_bf16x2(a[2], a[3]);
                uint32_t l0 = pack_bf16x2(a[0] - __uint_as_float(h0 << 16),
                                          a[1] - __uint_as_float(h0 & 0xffff0000u));
                uint32_t l1 = pack_bf16x2(a[2] - __uint_as_float(h1 << 16),
                                          a[3] - __uint_as_float(h1 & 0xffff0000u));
                *(uint32_t*)(vh + o0) = h0;
                *(uint32_t*)(vh + o0 + 8 * EMB) = h1;
                *(uint32_t*)(vl + o0) = l0;
                *(uint32_t*)(vl + o0 + 8 * EMB) = l1;
            }
        }
        return;
    }

    // ---- Q/K: fused RoPE + RMSNorm + bf16 split ----
    float* Cs = (float*)smc;            // 128 x 257 fp32 = 131584 B
#pragma unroll
    for (int mf = 0; mf < 4; mf++) {
#pragma unroll
        for (int nf = 0; nf < 8; nf++) {
            const float* a = acc[mf][nf];
            float* p0 = Cs + (rloc + mf * 16) * CSTR + nloc + nf * 8;
            p0[0] = a[0]; p0[1] = a[1];
            p0[8 * CSTR] = a[2]; p0[8 * CSTR + 1] = a[3];
        }
    }
    __syncthreads();

    {
        const int r  = t & 127;
        const int hh = t >> 7;          // 0 or 1 (two heads per tile)
        float* row = Cs + r * CSTR + hh * 128;
        const int tp = (row0 + r) & (SEQ - 1);
        const float* ctr = ct + tp * 64;
        const float* str = st + tp * 64;

        float sq = 0.f;
#pragma unroll 8
        for (int i = 0; i < 64; i++) {
            const float x1 = row[i], x2 = row[64 + i];
            const float c = ctr[i], s = str[i];
            const float n1 = x1 * c - x2 * s;
            const float n2 = x1 * s + x2 * c;
            sq += n1 * n1 + n2 * n2;
            row[i] = n1;
            row[64 + i] = n2;
        }
        const float osc = (whichCTA == 0) ? 0.08838834764831845f : 1.0f;
        const float rs = rsqrtf(sq * (1.0f / 128.0f) + RMS_EPS) * osc;

        __nv_bfloat16* dh = (whichCTA == 0) ? qh : kh;
        __nv_bfloat16* dl = (whichCTA == 0) ? ql : kl;
        const size_t base = (size_t)(row0 + r) * EMB + (col0 & 2047) + hh * 128;
#pragma unroll 8
        for (int j = 0; j < 64; j++) {
            const float y0 = row[2 * j] * rs;
            const float y1 = row[2 * j + 1] * rs;
            const uint32_t hp = pack_bf16x2(y0, y1);
            const uint32_t lp = pack_bf16x2(y0 - __uint_as_float(hp << 16),
                                            y1 - __uint_as_float(hp & 0xffff0000u));
            *(uint32_t*)(dh + base + 2 * j) = hp;
            *(uint32_t*)(dl + base + 2 * j) = lp;
        }
    }
}

// =====================================================================
// Flash attention on mma.sync bf16 (split hi/lo, 3 chains both GEMMs).
// Output written directly as bf16 hi/lo for the WO GEMM.
// =====================================================================
#define FL_STR  136
#define FL_ROWB (FL_STR*2)
#define FL_TILE (64*FL_ROWB)
#define FL_STG  (4*FL_TILE)
#define FL_QLO  (128*FL_ROWB)
#define FL_SMEM (3*FL_STG)

__global__ __launch_bounds__(256, 1) void flash_mma_kernel(
    const __nv_bfloat16* __restrict__ Qh, const __nv_bfloat16* __restrict__ Ql,
    const __nv_bfloat16* __restrict__ Kh, const __nv_bfloat16* __restrict__ Kl,
    const __nv_bfloat16* __restrict__ Vh, const __nv_bfloat16* __restrict__ Vl,
    __nv_bfloat16* __restrict__ Yh, __nv_bfloat16* __restrict__ Yl)
{
    extern __shared__ char smc[];
    const uint32_t sb = smem_to_u32(smc);
    const int t = threadIdx.x;
    const int lane = t & 31;
    const int w = t >> 5;
    const int qi = gridDim.x - 1 - blockIdx.x;
    const int h = blockIdx.y, b = blockIdx.z;
    const int qs = qi * 128;
    const size_t hb = ((size_t)b * SEQ) * EMB + (size_t)h * HDIM;

#pragma unroll
    for (int i = 0; i < 8; i++) {
        const int idx = t + i * 256;
        const int r = idx >> 4, c = idx & 15;
        const size_t g = hb + (size_t)(qs + r) * EMB + c * 8;
        CP_ASYNC16(sb + r * FL_ROWB + c * 16, Qh + g);
        CP_ASYNC16(sb + FL_QLO + r * FL_ROWB + c * 16, Ql + g);
    }
    CP_COMMIT();

    auto load_kv = [&](int s, int ks) {
        const uint32_t base = sb + FL_STG * (1 + s);
        const __nv_bfloat16* srcs[4] = {Kh, Kl, Vh, Vl};
#pragma unroll
        for (int tile = 0; tile < 4; tile++) {
#pragma unroll
            for (int i = 0; i < 4; i++) {
                const int idx = t + i * 256;
                const int r = idx >> 4, c = idx & 15;
                CP_ASYNC16(base + tile * FL_TILE + r * FL_ROWB + c * 16,
                           srcs[tile] + hb + (size_t)(ks + r) * EMB + c * 8);
            }
        }
    };

    load_kv(0, 0);
    CP_COMMIT();

    float m0 = -INFINITY, m1 = -INFINITY, l0 = 0.f, l1 = 0.f;
    float o[16][4];
#pragma unroll
    for (int i = 0; i < 16; i++)
#pragma unroll
        for (int j = 0; j < 4; j++) o[i][j] = 0.f;

    const uint32_t q_addr = sb + (w * 16 + (lane & 15)) * FL_ROWB + (lane >> 4) * 16;
    const int krow = (lane & 7) + ((lane >> 4) << 3);
    const uint32_t kcolb = ((lane >> 3) & 1) * 16;
    const int vrow = (lane & 7) + (((lane >> 3) & 1) << 3);
    const uint32_t vcolb = (lane >> 4) * 16;

    const int r0g = qs + w * 16 + (lane >> 2);
    const int r1g = r0g + 8;
    const int nkt = (qs + 128) / 64;

    for (int jt = 0; jt < nkt; jt++) {
        CP_WAIT0();
        __syncthreads();
        if (jt + 1 < nkt) { load_kv((jt + 1) & 1, (jt + 1) * 64); CP_COMMIT(); }

        const int ks = jt * 64;
        if (ks <= qs + w * 16 + 15) {
            const uint32_t kb = sb + FL_STG * (1 + (jt & 1));

            float s[8][4];
#pragma unroll
            for (int i = 0; i < 8; i++)
#pragma unroll
                for (int j = 0; j < 4; j++) s[i][j] = 0.f;

#pragma unroll
            for (int kf = 0; kf < 8; kf++) {
                uint32_t qa[4], qla[4];
                ldsm4(qa, q_addr + kf * 32);
                ldsm4(qla, q_addr + FL_QLO + kf * 32);
#pragma unroll
                for (int nfp = 0; nfp < 4; nfp++) {
                    uint32_t kh4[4], kl4[4];
                    const uint32_t ka = kb + (nfp * 16 + krow) * FL_ROWB + kcolb + kf * 32;
                    ldsm4(kh4, ka);
                    ldsm4(kl4, ka + FL_TILE);
                    mma_bf16(s[2 * nfp], qa, kh4);
                    mma_bf16(s[2 * nfp], qa, kl4);
                    mma_bf16(s[2 * nfp], qla, kh4);
                    mma_bf16(s[2 * nfp + 1], qa, kh4 + 2);
                    mma_bf16(s[2 * nfp + 1], qa, kl4 + 2);
                    mma_bf16(s[2 * nfp + 1], qla, kh4 + 2);
                }
            }

            if (ks + 63 > r0g) {
#pragma unroll
                for (int nf = 0; nf < 8; nf++) {
                    const int kc = ks + nf * 8 + (lane & 3) * 2;
                    if (kc > r0g)     s[nf][0] = -1e30f;
                    if (kc + 1 > r0g) s[nf][1] = -1e30f;
                    if (kc > r1g)     s[nf][2] = -1e30f;
                    if (kc + 1 > r1g) s[nf][3] = -1e30f;
                }
            }

            float m0l = -INFINITY, m1l = -INFINITY;
#pragma unroll
            for (int nf = 0; nf < 8; nf++) {
                m0l = fmaxf(m0l, fmaxf(s[nf][0], s[nf][1]));
                m1l = fmaxf(m1l, fmaxf(s[nf][2], s[nf][3]));
            }
            m0l = fmaxf(m0l, __shfl_xor_sync(0xffffffffu, m0l, 1));
            m0l = fmaxf(m0l, __shfl_xor_sync(0xffffffffu, m0l, 2));
            m1l = fmaxf(m1l, __shfl_xor_sync(0xffffffffu, m1l, 1));
            m1l = fmaxf(m1l, __shfl_xor_sync(0xffffffffu, m1l, 2));
            const float m0n = fmaxf(m0, m0l), m1n = fmaxf(m1, m1l);
            const float a0 = ex2((m0 - m0n) * L2E);
            const float a1 = ex2((m1 - m1n) * L2E);
            m0 = m0n; m1 = m1n;

            float sum0 = 0.f, sum1 = 0.f;
#pragma unroll
            for (int nf = 0; nf < 8; nf++) {
                s[nf][0] = ex2((s[nf][0] - m0n) * L2E); sum0 += s[nf][0];
                s[nf][1] = ex2((s[nf][1] - m0n) * L2E); sum0 += s[nf][1];
                s[nf][2] = ex2((s[nf][2] - m1n) * L2E); sum1 += s[nf][2];
                s[nf][3] = ex2((s[nf][3] - m1n) * L2E); sum1 += s[nf][3];
            }
            sum0 += __shfl_xor_sync(0xffffffffu, sum0, 1);
            sum0 += __shfl_xor_sync(0xffffffffu, sum0, 2);
            sum1 += __shfl_xor_sync(0xffffffffu, sum1, 1);
            sum1 += __shfl_xor_sync(0xffffffffu, sum1, 2);
            l0 = l0 * a0 + sum0;
            l1 = l1 * a1 + sum1;

#pragma unroll
            for (int nf = 0; nf < 16; nf++) {
                o[nf][0] *= a0; o[nf][1] *= a0;
                o[nf][2] *= a1; o[nf][3] *= a1;
            }

            const uint32_t vb = kb + 2 * FL_TILE;
#pragma unroll
            for (int kf2 = 0; kf2 < 4; kf2++) {
                uint32_t ah[4], al[4];
#pragma unroll
                for (int q2 = 0; q2 < 2; q2++) {
                    const float* sp = s[2 * kf2 + q2];
#pragma unroll
                    for (int rr = 0; rr < 2; rr++) {
                        const float pe = sp[rr * 2], po = sp[rr * 2 + 1];
                        const uint32_t ph = pack_bf16x2(pe, po);
                        const float rle = pe - __uint_as_float(ph << 16);
                        const float rlo = po - __uint_as_float(ph & 0xffff0000u);
                        ah[q2 * 2 + rr] = ph;
                        al[q2 * 2 + rr] = pack_bf16x2(rle, rlo);
                    }
                }
#pragma unroll
                for (int nfp = 0; nfp < 8; nfp++) {
                    uint32_t vh4[4], vl4[4];
                    const uint32_t va = vb + (kf2 * 16 + vrow) * FL_ROWB + vcolb + nfp * 32;
                    ldsm4t(vh4, va);
                    ldsm4t(vl4, va + FL_TILE);
                    mma_bf16(o[2 * nfp], ah, vh4);
                    mma_bf16(o[2 * nfp], ah, vl4);
                    mma_bf16(o[2 * nfp], al, vh4);
                    mma_bf16(o[2 * nfp + 1], ah, vh4 + 2);
                    mma_bf16(o[2 * nfp + 1], ah, vl4 + 2);
                    mma_bf16(o[2 * nfp + 1], al, vh4 + 2);
                }
            }
        }
    }

    const float il0 = 1.f / l0, il1 = 1.f / l1;
    const size_t yb = hb + (size_t)r0g * EMB + (lane & 3) * 2;
#pragma unroll
    for (int nf = 0; nf < 16; nf++) {
        const float a0v = o[nf][0] * il0, a1v = o[nf][1] * il0;
        const float b0v = o[nf][2] * il1, b1v = o[nf][3] * il1;
        const uint32_t h0 = pack_bf16x2(a0v, a1v);
        const uint32_t h1 = pack_bf16x2(b0v, b1v);
        const uint32_t q0 = pack_bf16x2(a0v - __uint_as_float(h0 << 16),
                                        a1v - __uint_as_float(h0 & 0xffff0000u));
        const uint32_t q1 = pack_bf16x2(b0v - __uint_as_float(h1 << 16),
                                        b1v - __uint_as_float(h1 & 0xffff0000u));
        *(uint32_t*)(Yh + yb + nf * 8) = h0;
        *(uint32_t*)(Yl + yb + nf * 8) = q0;
        *(uint32_t*)(Yh + yb + (size_t)8 * EMB + nf * 8) = h1;
        *(uint32_t*)(Yl + yb + (size_t)8 * EMB + nf * 8) = q1;
    }
}

// =====================================================================
// launch
// =====================================================================
extern "C" void kernel_launch(void* const* d_in, const int* in_sizes, int n_in,
                              void* d_out, int out_size)
{
    const float* x  = (const float*)d_in[0];
    const float* wq = (const float*)d_in[1];
    const float* wk = (const float*)d_in[2];
    const float* wv = (const float*)d_in[3];
    const float* wo = (const float*)d_in[4];
    float* out = (float*)d_out;

    float *ct, *st;
    __nv_bfloat16 *ahi, *alo, *wthi, *wtlo, *qh, *ql, *kh, *kl, *vh, *vl;
    cudaGetSymbolAddress((void**)&ct, g_cos);
    cudaGetSymbolAddress((void**)&st, g_sin);
    cudaGetSymbolAddress((void**)&ahi, g_ahi);
    cudaGetSymbolAddress((void**)&alo, g_alo);
    cudaGetSymbolAddress((void**)&wthi, g_wthi);
    cudaGetSymbolAddress((void**)&wtlo, g_wtlo);
    cudaGetSymbolAddress((void**)&qh, g_qh);
    cudaGetSymbolAddress((void**)&ql, g_ql);
    cudaGetSymbolAddress((void**)&kh, g_kh);
    cudaGetSymbolAddress((void**)&kl, g_kl);
    cudaGetSymbolAddress((void**)&vh, g_vh);
    cudaGetSymbolAddress((void**)&vl, g_vl);

    cudaFuncSetAttribute(mma_gemm_kernel,
                         cudaFuncAttributeMaxDynamicSharedMemorySize, GEMM_SMEM);
    cudaFuncSetAttribute(flash_mma_kernel,
                         cudaFuncAttributeMaxDynamicSharedMemorySize, FL_SMEM);

    const int n4 = (int)(ELEMS / 4);
    const dim3 sgrid((n4 + 255) / 256);
    const size_t WSZ = (size_t)EMB * EMB;

    // prep: rope tables, split x, all 4 weights (q,k,v,o) in one launch
    rope_table_kernel<<<(SEQ * 64 + 255) / 256, 256>>>(ct, st);
    split_kernel<<<sgrid, 256>>>(x, ahi, alo, n4);
    dim3 wgrid(EMB / 32, EMB / 32, 4);
    wsplit4_kernel<<<wgrid, 256>>>(wq, wk, wv, wo, wthi, wtlo);

    // fused QKV GEMM + RoPE/RMS/split epilogue (Q,K) + direct V split
    dim3 qkvgrid(3 * EMB / BN, MROWS / BM);   // (24, 64)
    mma_gemm_kernel<<<qkvgrid, 256, GEMM_SMEM>>>(
        ahi, alo, wthi, wtlo, EMB, 1,
        nullptr, qh, ql, kh, kl, vh, vl, ct, st);

    // flash attention -> writes ahi/alo (bf16 hi/lo) directly
    dim3 fgrid(SEQ / 128, NHEAD, BATCH);
    flash_mma_kernel<<<fgrid, 256, FL_SMEM>>>(qh, ql, kh, kl, vh, vl, ahi, alo);

    // out = y @ wo
    dim3 ogrid(EMB / BN, MROWS / BM);
    mma_gemm_kernel<<<ogrid, 256, GEMM_SMEM>>>(
        ahi, alo, wthi + 3 * WSZ, wtlo + 3 * WSZ, EMB, 0,
        out, nullptr, nullptr, nullptr, nullptr, nullptr, nullptr, nullptr, nullptr);
}

// round 8
// speedup vs baseline: 1.0439x; 1.0439x over previous
#include <cuda_runtime.h>
#include <cuda_bf16.h>
#include <math.h>
#include <stdint.h>

// ---------------- constants ----------------
#define BATCH 4
#define SEQ   2048
#define EMB   2048
#define NHEAD 16
#define HDIM  128
#define MROWS (BATCH*SEQ)               // 8192
#define ELEMS ((size_t)BATCH*SEQ*EMB)   // 16777216
#define L2E   1.4426950408889634f
#define RMS_EPS 1.1920929e-07f

// ---------------- scratch (device globals: allocation-free) ----------------
__device__ float g_q[ELEMS];
__device__ float g_k[ELEMS];
__device__ __nv_bfloat16 g_ahi[ELEMS];
__device__ __nv_bfloat16 g_alo[ELEMS];
__device__ __nv_bfloat16 g_wthi[(size_t)4*EMB*EMB];
__device__ __nv_bfloat16 g_wtlo[(size_t)4*EMB*EMB];
__device__ __nv_bfloat16 g_qh[ELEMS];
__device__ __nv_bfloat16 g_ql[ELEMS];
__device__ __nv_bfloat16 g_kh[ELEMS];
__device__ __nv_bfloat16 g_kl[ELEMS];
__device__ __nv_bfloat16 g_vh[ELEMS];
__device__ __nv_bfloat16 g_vl[ELEMS];
__device__ float g_cos[SEQ*64];
__device__ float g_sin[SEQ*64];

// =====================================================================
// PTX helpers (standard sm_80+ instructions; valid on plain sm_103)
// =====================================================================
__device__ __forceinline__ uint32_t smem_to_u32(const void* p) {
    uint32_t a;
    asm("{ .reg .u64 t; cvta.to.shared.u64 t, %1; cvt.u32.u64 %0, t; }"
        : "=r"(a) : "l"(p));
    return a;
}

__device__ __forceinline__ void ldsm4(uint32_t* r, uint32_t addr) {
    asm volatile("ldmatrix.sync.aligned.m8n8.x4.shared.b16 {%0,%1,%2,%3}, [%4];"
        : "=r"(r[0]), "=r"(r[1]), "=r"(r[2]), "=r"(r[3]) : "r"(addr));
}
__device__ __forceinline__ void ldsm4t(uint32_t* r, uint32_t addr) {
    asm volatile("ldmatrix.sync.aligned.m8n8.x4.trans.shared.b16 {%0,%1,%2,%3}, [%4];"
        : "=r"(r[0]), "=r"(r[1]), "=r"(r[2]), "=r"(r[3]) : "r"(addr));
}

__device__ __forceinline__ void mma_bf16(float* c, const uint32_t* a, const uint32_t* b) {
    asm volatile(
        "mma.sync.aligned.m16n8k16.row.col.f32.bf16.bf16.f32 "
        "{%0,%1,%2,%3}, {%4,%5,%6,%7}, {%8,%9}, {%0,%1,%2,%3};"
        : "+f"(c[0]), "+f"(c[1]), "+f"(c[2]), "+f"(c[3])
        : "r"(a[0]), "r"(a[1]), "r"(a[2]), "r"(a[3]), "r"(b[0]), "r"(b[1]));
}

__device__ __forceinline__ uint32_t pack_bf16x2(float lo, float hi) {
    uint32_t r;
    asm("cvt.rn.bf16x2.f32 %0, %1, %2;" : "=r"(r) : "f"(hi), "f"(lo));
    return r;
}

// fast exp2 (single SASS MUFU.EX2)
__device__ __forceinline__ float ex2(float x) {
    float y;
    asm("ex2.approx.f32 %0, %1;" : "=f"(y) : "f"(x));
    return y;
}

#define CP_ASYNC16(dst, src) \
    asm volatile("cp.async.cg.shared.global [%0], [%1], 16;" :: "r"(dst), "l"(src) : "memory")
#define CP_COMMIT() asm volatile("cp.async.commit_group;" ::: "memory")
#define CP_WAIT1()  asm volatile("cp.async.wait_group 1;" ::: "memory")
#define CP_WAIT0()  asm volatile("cp.async.wait_group 0;" ::: "memory")

// =====================================================================
// split: fp32 -> bf16 hi + bf16 lo (residual)
// =====================================================================
__global__ __launch_bounds__(256) void split_kernel(
    const float* __restrict__ in,
    __nv_bfloat16* __restrict__ hi, __nv_bfloat16* __restrict__ lo, int n4)
{
    int i = blockIdx.x * 256 + threadIdx.x;
    if (i >= n4) return;
    float4 v = ((const float4*)in)[i];
    __nv_bfloat16 h0 = __float2bfloat16(v.x);
    __nv_bfloat16 h1 = __float2bfloat16(v.y);
    __nv_bfloat16 h2 = __float2bfloat16(v.z);
    __nv_bfloat16 h3 = __float2bfloat16(v.w);
    __nv_bfloat16 l0 = __float2bfloat16(v.x - __bfloat162float(h0));
    __nv_bfloat16 l1 = __float2bfloat16(v.y - __bfloat162float(h1));
    __nv_bfloat16 l2 = __float2bfloat16(v.z - __bfloat162float(h2));
    __nv_bfloat16 l3 = __float2bfloat16(v.w - __bfloat162float(h3));
    __nv_bfloat162* hp = (__nv_bfloat162*)(hi + 4 * (size_t)i);
    __nv_bfloat162* lp = (__nv_bfloat162*)(lo + 4 * (size_t)i);
    hp[0] = __nv_bfloat162(h0, h1); hp[1] = __nv_bfloat162(h2, h3);
    lp[0] = __nv_bfloat162(l0, l1); lp[1] = __nv_bfloat162(l2, l3);
}

// =====================================================================
// 4 weights at once: transpose + split, blockIdx.z selects the weight
// =====================================================================
__global__ __launch_bounds__(256) void wsplit4_kernel(
    const float* __restrict__ w0, const float* __restrict__ w1,
    const float* __restrict__ w2, const float* __restrict__ w3,
    __nv_bfloat16* __restrict__ hi_base, __nv_bfloat16* __restrict__ lo_base)
{
    __shared__ float tile[32][33];
    const int z = blockIdx.z;
    const float* w = (z == 0) ? w0 : (z == 1) ? w1 : (z == 2) ? w2 : w3;
    __nv_bfloat16* hi = hi_base + (size_t)z * EMB * EMB;
    __nv_bfloat16* lo = lo_base + (size_t)z * EMB * EMB;

    int n0 = blockIdx.x * 32, k0 = blockIdx.y * 32;
    int tx = threadIdx.x & 31, ty = threadIdx.x >> 5;
#pragma unroll
    for (int i = 0; i < 32; i += 8)
        tile[ty + i][tx] = w[(size_t)(k0 + ty + i) * EMB + n0 + tx];
    __syncthreads();
#pragma unroll
    for (int i = 0; i < 32; i += 8) {
        float v = tile[tx][ty + i];
        __nv_bfloat16 h = __float2bfloat16(v);
        size_t o = (size_t)(n0 + ty + i) * EMB + k0 + tx;
        hi[o] = h;
        lo[o] = __float2bfloat16(v - __bfloat162float(h));
    }
}

// =====================================================================
// RoPE table precompute (double precision, once)
// =====================================================================
__global__ __launch_bounds__(256) void rope_table_kernel(
    float* __restrict__ ct, float* __restrict__ st)
{
    const int idx = blockIdx.x * 256 + threadIdx.x;
    if (idx >= SEQ * 64) return;
    const int tp = idx >> 6, i = idx & 63;
    double inv = exp(-((double)i / 64.0) * log(10000.0));
    double ang = (double)tp * inv;
    double sd, cd;
    sincos(ang, &sd, &cd);
    ct[idx] = (float)cd;
    st[idx] = (float)sd;
}

// =====================================================================
// mma.sync GEMM: C = A * B^T, split bf16 3-chain, 2-stage cp.async.
// Block tile 128x256x64, 8 warps (2 x 4), warp tile 64x64.
// mode 0: write fp32 to c0 (row stride EMB).
// mode 1: QKV fused (N=6144): n<2048 -> c0 fp32, <4096 -> c1 fp32,
//         else V written directly as bf16 hi/lo (c2h/c2l).
// =====================================================================
#define BM 128
#define BN 256
#define BK 64
#define RSTRB 144
#define TA (128 * RSTRB)          // 18432
#define TB (256 * RSTRB)          // 36864
#define STG_B (2*TA + 2*TB)       // 110592
#define GEMM_SMEM (2 * STG_B)     // 221184

__global__ __launch_bounds__(256) void mma_gemm_kernel(
    const __nv_bfloat16* __restrict__ Ahi, const __nv_bfloat16* __restrict__ Alo,
    const __nv_bfloat16* __restrict__ Bhi, const __nv_bfloat16* __restrict__ Blo,
    int K, int mode,
    float* __restrict__ c0, float* __restrict__ c1,
    __nv_bfloat16* __restrict__ c2h, __nv_bfloat16* __restrict__ c2l)
{
    extern __shared__ char smc[];
    const uint32_t sb = smem_to_u32(smc);
    const int t = threadIdx.x;
    const int lane = t & 31;
    const int wid = t >> 5;
    const int warp_m = wid & 1;
    const int warp_n = wid >> 1;
    const int row0 = blockIdx.y * BM;
    const int col0 = blockIdx.x * BN;

    float acc[4][8][4];
#pragma unroll
    for (int i = 0; i < 4; i++)
#pragma unroll
        for (int j = 0; j < 8; j++)
#pragma unroll
            for (int r = 0; r < 4; r++) acc[i][j][r] = 0.f;

    auto load_stage = [&](int s, int k0) {
        const uint32_t base = sb + s * STG_B;
#pragma unroll
        for (int i = 0; i < 4; i++) {
            const int idx = t + i * 256;
            const int r = idx >> 3, c = idx & 7;
            const size_t g = (size_t)(row0 + r) * K + k0 + c * 8;
            const uint32_t d = base + r * RSTRB + c * 16;
            CP_ASYNC16(d, Ahi + g);
            CP_ASYNC16(d + TA, Alo + g);
        }
#pragma unroll
        for (int i = 0; i < 8; i++) {
            const int idx = t + i * 256;
            const int r = idx >> 3, c = idx & 7;
            const size_t g = (size_t)(col0 + r) * K + k0 + c * 8;
            const uint32_t d = base + 2 * TA + r * RSTRB + c * 16;
            CP_ASYNC16(d, Bhi + g);
            CP_ASYNC16(d + TB, Blo + g);
        }
    };

    const int nIter = K / BK;
    load_stage(0, 0);
    CP_COMMIT();

    for (int it = 0; it < nIter; it++) {
        if (it + 1 < nIter) {
            load_stage((it + 1) & 1, (it + 1) * BK);
            CP_COMMIT();
            CP_WAIT1();
        } else {
            CP_WAIT0();
        }
        __syncthreads();

        const uint32_t abase = sb + (it & 1) * STG_B;
        const uint32_t bbase = abase + 2 * TA;
        const int arow = warp_m * 64 + (lane & 15);
        const int brow = warp_n * 64 + ((lane >> 4) << 3) + (lane & 7);

#pragma unroll
        for (int ks = 0; ks < 4; ks++) {
            uint32_t ah[4][4], al[4][4], bh[4][4], bl[4][4];
            const uint32_t acol = ks * 32 + ((lane >> 4) << 4);
            const uint32_t bcol = ks * 32 + (((lane >> 3) & 1) << 4);
#pragma unroll
            for (int mf = 0; mf < 4; mf++) {
                const uint32_t ad = abase + (arow + mf * 16) * RSTRB + acol;
                ldsm4(ah[mf], ad);
                ldsm4(al[mf], ad + TA);
            }
#pragma unroll
            for (int bf = 0; bf < 4; bf++) {
                const uint32_t bd = bbase + (brow + bf * 16) * RSTRB + bcol;
                ldsm4(bh[bf], bd);
                ldsm4(bl[bf], bd + TB);
            }
#pragma unroll
            for (int mf = 0; mf < 4; mf++) {
#pragma unroll
                for (int nf = 0; nf < 8; nf++) {
                    const uint32_t* bhp = &bh[nf >> 1][(nf & 1) * 2];
                    const uint32_t* blp = &bl[nf >> 1][(nf & 1) * 2];
                    mma_bf16(acc[mf][nf], ah[mf], bhp);
                    mma_bf16(acc[mf][nf], ah[mf], blp);
                    mma_bf16(acc[mf][nf], al[mf], bhp);
                }
            }
        }
        __syncthreads();
    }

    // ---- epilogue ----
    const int mbase = row0 + warp_m * 64 + (lane >> 2);
    const int nb = col0 + warp_n * 64 + (lane & 3) * 2;
#pragma unroll
    for (int mf = 0; mf < 4; mf++) {
#pragma unroll
        for (int nf = 0; nf < 8; nf++) {
            const int n = nb + nf * 8;
            const int m0 = mbase + mf * 16;
            const float* a = acc[mf][nf];
            if (mode == 0) {
                const size_t o0 = (size_t)m0 * EMB + n;
                *(float2*)(c0 + o0) = make_float2(a[0], a[1]);
                *(float2*)(c0 + o0 + 8 * EMB) = make_float2(a[2], a[3]);
            } else {
                const int which = n >> 11;
                const int nloc = n & 2047;
                const size_t o0 = (size_t)m0 * EMB + nloc;
                if (which == 0) {
                    *(float2*)(c0 + o0) = make_float2(a[0], a[1]);
                    *(float2*)(c0 + o0 + 8 * EMB) = make_float2(a[2], a[3]);
                } else if (which == 1) {
                    *(float2*)(c1 + o0) = make_float2(a[0], a[1]);
                    *(float2*)(c1 + o0 + 8 * EMB) = make_float2(a[2], a[3]);
                } else {
                    uint32_t h0 = pack_bf16x2(a[0], a[1]);
                    uint32_t h1 = pack_bf16x2(a[2], a[3]);
                    uint32_t l0 = pack_bf16x2(a[0] - __uint_as_float(h0 << 16),
                                              a[1] - __uint_as_float(h0 & 0xffff0000u));
                    uint32_t l1 = pack_bf16x2(a[2] - __uint_as_float(h1 << 16),
                                              a[3] - __uint_as_float(h1 & 0xffff0000u));
                    *(uint32_t*)(c2h + o0) = h0;
                    *(uint32_t*)(c2h + o0 + 8 * EMB) = h1;
                    *(uint32_t*)(c2l + o0) = l0;
                    *(uint32_t*)(c2l + o0 + 8 * EMB) = l1;
                }
            }
        }
    }
}

// =====================================================================
// RoPE + RMSNorm + scale + bf16 hi/lo split (table-based, pure fp32)
// =====================================================================
__global__ void ropeprep_kernel(const float* __restrict__ buf,
                                const float* __restrict__ ct,
                                const float* __restrict__ st,
                                __nv_bfloat16* __restrict__ hi,
                                __nv_bfloat16* __restrict__ lo,
                                float outscale)
{
    const int h = blockIdx.x, tp = blockIdx.y, b = blockIdx.z;
    const int i = threadIdx.x;  // 0..63
    const size_t base = ((size_t)b * SEQ + tp) * EMB + (size_t)h * HDIM;

    float x1 = buf[base + i];
    float x2 = buf[base + 64 + i];

    const float c = ct[tp * 64 + i];
    const float s = st[tp * 64 + i];

    float n1 = x1 * c - x2 * s;
    float n2 = x1 * s + x2 * c;

    float sq = n1 * n1 + n2 * n2;
#pragma unroll
    for (int o = 16; o > 0; o >>= 1)
        sq += __shfl_xor_sync(0xffffffffu, sq, o);

    __shared__ float partial[2];
    if ((i & 31) == 0) partial[i >> 5] = sq;
    __syncthreads();
    float tot = partial[0] + partial[1];
    float r = rsqrtf(tot * (1.0f / 128.0f) + RMS_EPS) * outscale;

    float y1 = n1 * r, y2 = n2 * r;
    __nv_bfloat16 h1 = __float2bfloat16(y1);
    __nv_bfloat16 h2 = __float2bfloat16(y2);
    hi[base + i]      = h1;
    hi[base + 64 + i] = h2;
    lo[base + i]      = __float2bfloat16(y1 - __bfloat162float(h1));
    lo[base + 64 + i] = __float2bfloat16(y2 - __bfloat162float(h2));
}

// =====================================================================
// Flash attention on mma.sync bf16 (split hi/lo, 3 chains both GEMMs).
// Output written directly as bf16 hi/lo for the WO GEMM.
// =====================================================================
#define FL_STR  136
#define FL_ROWB (FL_STR*2)
#define FL_TILE (64*FL_ROWB)
#define FL_STG  (4*FL_TILE)
#define FL_QLO  (128*FL_ROWB)
#define FL_SMEM (3*FL_STG)

__global__ __launch_bounds__(256, 1) void flash_mma_kernel(
    const __nv_bfloat16* __restrict__ Qh, const __nv_bfloat16* __restrict__ Ql,
    const __nv_bfloat16* __restrict__ Kh, const __nv_bfloat16* __restrict__ Kl,
    const __nv_bfloat16* __restrict__ Vh, const __nv_bfloat16* __restrict__ Vl,
    __nv_bfloat16* __restrict__ Yh, __nv_bfloat16* __restrict__ Yl)
{
    extern __shared__ char smc[];
    const uint32_t sb = smem_to_u32(smc);
    const int t = threadIdx.x;
    const int lane = t & 31;
    const int w = t >> 5;
    const int qi = gridDim.x - 1 - blockIdx.x;
    const int h = blockIdx.y, b = blockIdx.z;
    const int qs = qi * 128;
    const size_t hb = ((size_t)b * SEQ) * EMB + (size_t)h * HDIM;

#pragma unroll
    for (int i = 0; i < 8; i++) {
        const int idx = t + i * 256;
        const int r = idx >> 4, c = idx & 15;
        const size_t g = hb + (size_t)(qs + r) * EMB + c * 8;
        CP_ASYNC16(sb + r * FL_ROWB + c * 16, Qh + g);
        CP_ASYNC16(sb + FL_QLO + r * FL_ROWB + c * 16, Ql + g);
    }
    CP_COMMIT();

    auto load_kv = [&](int s, int ks) {
        const uint32_t base = sb + FL_STG * (1 + s);
        const __nv_bfloat16* srcs[4] = {Kh, Kl, Vh, Vl};
#pragma unroll
        for (int tile = 0; tile < 4; tile++) {
#pragma unroll
            for (int i = 0; i < 4; i++) {
                const int idx = t + i * 256;
                const int r = idx >> 4, c = idx & 15;
                CP_ASYNC16(base + tile * FL_TILE + r * FL_ROWB + c * 16,
                           srcs[tile] + hb + (size_t)(ks + r) * EMB + c * 8);
            }
        }
    };

    load_kv(0, 0);
    CP_COMMIT();

    float m0 = -INFINITY, m1 = -INFINITY, l0 = 0.f, l1 = 0.f;
    float o[16][4];
#pragma unroll
    for (int i = 0; i < 16; i++)
#pragma unroll
        for (int j = 0; j < 4; j++) o[i][j] = 0.f;

    const uint32_t q_addr = sb + (w * 16 + (lane & 15)) * FL_ROWB + (lane >> 4) * 16;
    const int krow = (lane & 7) + ((lane >> 4) << 3);
    const uint32_t kcolb = ((lane >> 3) & 1) * 16;
    const int vrow = (lane & 7) + (((lane >> 3) & 1) << 3);
    const uint32_t vcolb = (lane >> 4) * 16;

    const int r0g = qs + w * 16 + (lane >> 2);
    const int r1g = r0g + 8;
    const int nkt = (qs + 128) / 64;

    for (int jt = 0; jt < nkt; jt++) {
        CP_WAIT0();
        __syncthreads();
        if (jt + 1 < nkt) { load_kv((jt + 1) & 1, (jt + 1) * 64); CP_COMMIT(); }

        const int ks = jt * 64;
        if (ks <= qs + w * 16 + 15) {
            const uint32_t kb = sb + FL_STG * (1 + (jt & 1));

            float s[8][4];
#pragma unroll
            for (int i = 0; i < 8; i++)
#pragma unroll
                for (int j = 0; j < 4; j++) s[i][j] = 0.f;

#pragma unroll
            for (int kf = 0; kf < 8; kf++) {
                uint32_t qa[4], qla[4];
                ldsm4(qa, q_addr + kf * 32);
                ldsm4(qla, q_addr + FL_QLO + kf * 32);
#pragma unroll
                for (int nfp = 0; nfp < 4; nfp++) {
                    uint32_t kh4[4], kl4[4];
                    const uint32_t ka = kb + (nfp * 16 + krow) * FL_ROWB + kcolb + kf * 32;
                    ldsm4(kh4, ka);
                    ldsm4(kl4, ka + FL_TILE);
                    mma_bf16(s[2 * nfp], qa, kh4);
                    mma_bf16(s[2 * nfp], qa, kl4);
                    mma_bf16(s[2 * nfp], qla, kh4);
                    mma_bf16(s[2 * nfp + 1], qa, kh4 + 2);
                    mma_bf16(s[2 * nfp + 1], qa, kl4 + 2);
                    mma_bf16(s[2 * nfp + 1], qla, kh4 + 2);
                }
            }

            if (ks + 63 > r0g) {
#pragma unroll
                for (int nf = 0; nf < 8; nf++) {
                    const int kc = ks + nf * 8 + (lane & 3) * 2;
                    if (kc > r0g)     s[nf][0] = -1e30f;
                    if (kc + 1 > r0g) s[nf][1] = -1e30f;
                    if (kc > r1g)     s[nf][2] = -1e30f;
                    if (kc + 1 > r1g) s[nf][3] = -1e30f;
                }
            }

            float m0l = -INFINITY, m1l = -INFINITY;
#pragma unroll
            for (int nf = 0; nf < 8; nf++) {
                m0l = fmaxf(m0l, fmaxf(s[nf][0], s[nf][1]));
                m1l = fmaxf(m1l, fmaxf(s[nf][2], s[nf][3]));
            }
            m0l = fmaxf(m0l, __shfl_xor_sync(0xffffffffu, m0l, 1));
            m0l = fmaxf(m0l, __shfl_xor_sync(0xffffffffu, m0l, 2));
            m1l = fmaxf(m1l, __shfl_xor_sync(0xffffffffu, m1l, 1));
            m1l = fmaxf(m1l, __shfl_xor_sync(0xffffffffu, m1l, 2));
            const float m0n = fmaxf(m0, m0l), m1n = fmaxf(m1, m1l);
            const float a0 = ex2((m0 - m0n) * L2E);
            const float a1 = ex2((m1 - m1n) * L2E);
            m0 = m0n; m1 = m1n;

            float sum0 = 0.f, sum1 = 0.f;
#pragma unroll
            for (int nf = 0; nf < 8; nf++) {
                s[nf][0] = ex2((s[nf][0] - m0n) * L2E); sum0 += s[nf][0];
                s[nf][1] = ex2((s[nf][1] - m0n) * L2E); sum0 += s[nf][1];
                s[nf][2] = ex2((s[nf][2] - m1n) * L2E); sum1 += s[nf][2];
                s[nf][3] = ex2((s[nf][3] - m1n) * L2E); sum1 += s[nf][3];
            }
            sum0 += __shfl_xor_sync(0xffffffffu, sum0, 1);
            sum0 += __shfl_xor_sync(0xffffffffu, sum0, 2);
            sum1 += __shfl_xor_sync(0xffffffffu, sum1, 1);
            sum1 += __shfl_xor_sync(0xffffffffu, sum1, 2);
            l0 = l0 * a0 + sum0;
            l1 = l1 * a1 + sum1;

#pragma unroll
            for (int nf = 0; nf < 16; nf++) {
                o[nf][0] *= a0; o[nf][1] *= a0;
                o[nf][2] *= a1; o[nf][3] *= a1;
            }

            const uint32_t vb = kb + 2 * FL_TILE;
#pragma unroll
            for (int kf2 = 0; kf2 < 4; kf2++) {
                uint32_t ah[4], al[4];
#pragma unroll
                for (int q2 = 0; q2 < 2; q2++) {
                    const float* sp = s[2 * kf2 + q2];
#pragma unroll
                    for (int rr = 0; rr < 2; rr++) {
                        const float pe = sp[rr * 2], po = sp[rr * 2 + 1];
                        const uint32_t ph = pack_bf16x2(pe, po);
                        const float rle = pe - __uint_as_float(ph << 16);
                        const float rlo = po - __uint_as_float(ph & 0xffff0000u);
                        ah[q2 * 2 + rr] = ph;
                        al[q2 * 2 + rr] = pack_bf16x2(rle, rlo);
                    }
                }
#pragma unroll
                for (int nfp = 0; nfp < 8; nfp++) {
                    uint32_t vh4[4], vl4[4];
                    const uint32_t va = vb + (kf2 * 16 + vrow) * FL_ROWB + vcolb + nfp * 32;
                    ldsm4t(vh4, va);
                    ldsm4t(vl4, va + FL_TILE);
                    mma_bf16(o[2 * nfp], ah, vh4);
                    mma_bf16(o[2 * nfp], ah, vl4);
                    mma_bf16(o[2 * nfp], al, vh4);
                    mma_bf16(o[2 * nfp + 1], ah, vh4 + 2);
                    mma_bf16(o[2 * nfp + 1], ah, vl4 + 2);
                    mma_bf16(o[2 * nfp + 1], al, vh4 + 2);
                }
            }
        }
    }

    const float il0 = 1.f / l0, il1 = 1.f / l1;
    const size_t yb = hb + (size_t)r0g * EMB + (lane & 3) * 2;
#pragma unroll
    for (int nf = 0; nf < 16; nf++) {
        const float a0v = o[nf][0] * il0, a1v = o[nf][1] * il0;
        const float b0v = o[nf][2] * il1, b1v = o[nf][3] * il1;
        const uint32_t h0 = pack_bf16x2(a0v, a1v);
        const uint32_t h1 = pack_bf16x2(b0v, b1v);
        const uint32_t q0 = pack_bf16x2(a0v - __uint_as_float(h0 << 16),
                                        a1v - __uint_as_float(h0 & 0xffff0000u));
        const uint32_t q1 = pack_bf16x2(b0v - __uint_as_float(h1 << 16),
                                        b1v - __uint_as_float(h1 & 0xffff0000u));
        *(uint32_t*)(Yh + yb + nf * 8) = h0;
        *(uint32_t*)(Yl + yb + nf * 8) = q0;
        *(uint32_t*)(Yh + yb + (size_t)8 * EMB + nf * 8) = h1;
        *(uint32_t*)(Yl + yb + (size_t)8 * EMB + nf * 8) = q1;
    }
}

// =====================================================================
// launch
// =====================================================================
extern "C" void kernel_launch(void* const* d_in, const int* in_sizes, int n_in,
                              void* d_out, int out_size)
{
    const float* x  = (const float*)d_in[0];
    const float* wq = (const float*)d_in[1];
    const float* wk = (const float*)d_in[2];
    const float* wv = (const float*)d_in[3];
    const float* wo = (const float*)d_in[4];
    float* out = (float*)d_out;

    float *gq, *gk, *ct, *st;
    __nv_bfloat16 *ahi, *alo, *wthi, *wtlo, *qh, *ql, *kh, *kl, *vh, *vl;
    cudaGetSymbolAddress((void**)&gq, g_q);
    cudaGetSymbolAddress((void**)&gk, g_k);
    cudaGetSymbolAddress((void**)&ct, g_cos);
    cudaGetSymbolAddress((void**)&st, g_sin);
    cudaGetSymbolAddress((void**)&ahi, g_ahi);
    cudaGetSymbolAddress((void**)&alo, g_alo);
    cudaGetSymbolAddress((void**)&wthi, g_wthi);
    cudaGetSymbolAddress((void**)&wtlo, g_wtlo);
    cudaGetSymbolAddress((void**)&qh, g_qh);
    cudaGetSymbolAddress((void**)&ql, g_ql);
    cudaGetSymbolAddress((void**)&kh, g_kh);
    cudaGetSymbolAddress((void**)&kl, g_kl);
    cudaGetSymbolAddress((void**)&vh, g_vh);
    cudaGetSymbolAddress((void**)&vl, g_vl);

    cudaFuncSetAttribute(mma_gemm_kernel,
                         cudaFuncAttributeMaxDynamicSharedMemorySize, GEMM_SMEM);
    cudaFuncSetAttribute(flash_mma_kernel,
                         cudaFuncAttributeMaxDynamicSharedMemorySize, FL_SMEM);

    const int n4 = (int)(ELEMS / 4);
    const dim3 sgrid((n4 + 255) / 256);
    const size_t WSZ = (size_t)EMB * EMB;

    // prep: rope tables, split x, all 4 weights in one launch
    rope_table_kernel<<<(SEQ * 64 + 255) / 256, 256>>>(ct, st);
    split_kernel<<<sgrid, 256>>>(x, ahi, alo, n4);
    dim3 wgrid(EMB / 32, EMB / 32, 4);
    wsplit4_kernel<<<wgrid, 256>>>(wq, wk, wv, wo, wthi, wtlo);

    // fused QKV GEMM: q,k fp32; v directly bf16 hi/lo
    dim3 qkvgrid(3 * EMB / BN, MROWS / BM);   // (24, 64)
    mma_gemm_kernel<<<qkvgrid, 256, GEMM_SMEM>>>(
        ahi, alo, wthi, wtlo, EMB, 1, gq, gk, vh, vl);

    // RoPE + RMSNorm + split (scale folded into Q)
    dim3 rgrid(NHEAD, SEQ, BATCH);
    ropeprep_kernel<<<rgrid, 64>>>(gq, ct, st, qh, ql, 0.08838834764831845f);
    ropeprep_kernel<<<rgrid, 64>>>(gk, ct, st, kh, kl, 1.0f);

    // flash attention -> writes ahi/alo (bf16 hi/lo) directly
    dim3 fgrid(SEQ / 128, NHEAD, BATCH);
    flash_mma_kernel<<<fgrid, 256, FL_SMEM>>>(qh, ql, kh, kl, vh, vl, ahi, alo);

    // out = y @ wo
    dim3 ogrid(EMB / BN, MROWS / BM);
    mma_gemm_kernel<<<ogrid, 256, GEMM_SMEM>>>(
        ahi, alo, wthi + 3 * WSZ, wtlo + 3 * WSZ, EMB, 0,
        out, nullptr, nullptr, nullptr);
}